// round 1
// baseline (speedup 1.0000x reference)
#include <cuda_runtime.h>
#include <cuda_bf16.h>

// Problem constants
#define C_CH   64
#define NPAIRS 2080
#define NIN    2144          // 64 + 2080
#define OUT_CH 256
#define HW     4096          // 64*64 pixels per (b, channel)

// Tiling
#define BM 128
#define BN 128
#define BK 16
#define NTHREADS 256

// Pair tables: channel k of Y maps to x[ii[k]] * x[jj[k]]; jj==255 => linear (y = x[ii]).
__device__ unsigned char d_ii[NIN];
__device__ unsigned char d_jj[NIN];

__global__ void init_pairs_kernel() {
    int i = threadIdx.x;
    if (i < C_CH) {
        // linear channels 0..63
        d_ii[i] = (unsigned char)i;
        d_jj[i] = 255;
        // triu row i starts at 64 + 64*i - i*(i-1)/2   (row-major triu incl diagonal)
        int base = C_CH + C_CH * i - (i * (i - 1)) / 2;
        for (int j = i; j < C_CH; j++) {
            d_ii[base + (j - i)] = (unsigned char)i;
            d_jj[base + (j - i)] = (unsigned char)j;
        }
    }
}

// Out_b[256, 4096] = W[256, 2144] @ Y_b[2144, 4096], Y generated from x tile in smem.
__global__ __launch_bounds__(NTHREADS, 2)
void quad_gemm_kernel(const float* __restrict__ x,
                      const float* __restrict__ w,
                      float* __restrict__ out) {
    __shared__ float xs[C_CH][BN];   // 32 KB : x tile, all 64 channels x 128 pixels
    __shared__ float As[BK][BM];     // 8 KB  : W tile, transposed (k-major rows)
    __shared__ float Bs[BK][BN];     // 8 KB  : generated Y tile

    const int tid = threadIdx.x;
    const int b   = blockIdx.z;
    const int p0  = blockIdx.x * BN;   // pixel tile
    const int m0  = blockIdx.y * BM;   // output-channel tile

    const float* xb = x + (size_t)b * C_CH * HW;

    // ---- load x tile: 64 x 128 floats = 2048 float4, 8 per thread ----
    #pragma unroll
    for (int t = 0; t < 8; t++) {
        int e  = tid + t * NTHREADS;       // float4 index
        int c  = e >> 5;                   // channel row (128 floats = 32 float4 per row)
        int c4 = (e & 31) << 2;            // float offset in row
        float4 v = *reinterpret_cast<const float4*>(xb + (size_t)c * HW + p0 + c4);
        *reinterpret_cast<float4*>(&xs[c][c4]) = v;
    }

    const int tx = tid & 15;   // pixel group
    const int ty = tid >> 4;   // output group

    float acc[8][8];
    #pragma unroll
    for (int mi = 0; mi < 8; mi++)
        #pragma unroll
        for (int ni = 0; ni < 8; ni++)
            acc[mi][ni] = 0.0f;

    // Per-thread Y-build assignment (fixed across K-steps)
    const int k_row = tid >> 4;        // 0..15 : which k within the BK slab
    const int pb    = (tid & 15) * 8;  // 8 consecutive pixels

    for (int k0 = 0; k0 < NIN; k0 += BK) {
        __syncthreads();  // xs ready (iter 0) / previous compute done reading As,Bs

        // ---- load W tile -> As[kk][m] (transposed) : 512 float4, 2 per thread ----
        #pragma unroll
        for (int t = 0; t < 2; t++) {
            int e   = tid + t * NTHREADS;  // 0..511
            int m   = e >> 2;              // output row within tile
            int kk4 = (e & 3) << 2;        // k offset (float4 along k)
            float4 v = *reinterpret_cast<const float4*>(
                w + (size_t)(m0 + m) * NIN + k0 + kk4);
            As[kk4 + 0][m] = v.x;
            As[kk4 + 1][m] = v.y;
            As[kk4 + 2][m] = v.z;
            As[kk4 + 3][m] = v.w;
        }

        // ---- generate Y tile Bs[kk][p] from x tile ----
        {
            int k = k0 + k_row;
            int i = d_ii[k];
            int j = d_jj[k];
            float4 a0 = *reinterpret_cast<const float4*>(&xs[i][pb]);
            float4 a1 = *reinterpret_cast<const float4*>(&xs[i][pb + 4]);
            if (j != 255) {   // quadratic channel: multiply by x_j
                float4 b0 = *reinterpret_cast<const float4*>(&xs[j][pb]);
                float4 b1 = *reinterpret_cast<const float4*>(&xs[j][pb + 4]);
                a0.x *= b0.x; a0.y *= b0.y; a0.z *= b0.z; a0.w *= b0.w;
                a1.x *= b1.x; a1.y *= b1.y; a1.z *= b1.z; a1.w *= b1.w;
            }
            *reinterpret_cast<float4*>(&Bs[k_row][pb])     = a0;
            *reinterpret_cast<float4*>(&Bs[k_row][pb + 4]) = a1;
        }

        __syncthreads();  // As, Bs ready

        // ---- 128x128x16 compute, 8x8 per thread ----
        #pragma unroll
        for (int kk = 0; kk < BK; kk++) {
            float a[8], bb[8];
            *reinterpret_cast<float4*>(a)      = *reinterpret_cast<const float4*>(&As[kk][ty * 4]);
            *reinterpret_cast<float4*>(a + 4)  = *reinterpret_cast<const float4*>(&As[kk][ty * 4 + 64]);
            *reinterpret_cast<float4*>(bb)     = *reinterpret_cast<const float4*>(&Bs[kk][tx * 4]);
            *reinterpret_cast<float4*>(bb + 4) = *reinterpret_cast<const float4*>(&Bs[kk][tx * 4 + 64]);
            #pragma unroll
            for (int mi = 0; mi < 8; mi++)
                #pragma unroll
                for (int ni = 0; ni < 8; ni++)
                    acc[mi][ni] = fmaf(a[mi], bb[ni], acc[mi][ni]);
        }
    }

    // ---- epilogue: float4 stores, coalesced across tx ----
    float* ob = out + ((size_t)b * OUT_CH + m0) * HW + p0;
    #pragma unroll
    for (int mi = 0; mi < 8; mi++) {
        int m = ty * 4 + (mi & 3) + ((mi >> 2) << 6);
        float* orow = ob + (size_t)m * HW;
        float4 v0 = make_float4(acc[mi][0], acc[mi][1], acc[mi][2], acc[mi][3]);
        float4 v1 = make_float4(acc[mi][4], acc[mi][5], acc[mi][6], acc[mi][7]);
        *reinterpret_cast<float4*>(orow + tx * 4)      = v0;
        *reinterpret_cast<float4*>(orow + tx * 4 + 64) = v1;
    }
}

extern "C" void kernel_launch(void* const* d_in, const int* in_sizes, int n_in,
                              void* d_out, int out_size) {
    const float* x = (const float*)d_in[0];    // [B, 64, 64, 64] fp32
    const float* w = (const float*)d_in[1];    // [256, 2144] fp32
    float* out = (float*)d_out;                // [B, 256, 64, 64] fp32

    int B = in_sizes[0] / (C_CH * HW);

    init_pairs_kernel<<<1, 64>>>();

    dim3 grid(HW / BN, OUT_CH / BM, B);   // (32, 2, B)
    quad_gemm_kernel<<<grid, NTHREADS>>>(x, w, out);
}

// round 3
// speedup vs baseline: 3.6342x; 3.6342x over previous
#include <cuda_runtime.h>
#include <cuda_bf16.h>
#include <cstdint>

#define C_CH     64
#define NIN      2144
#define OUT_CH   256
#define HW       4096
#define KC       32
#define NCHUNK   67          // 2144 / 32
#define PX_CTA   128
#define NTH      512

// ---------------- prep storage (device globals) ----------------
// Pre-split W per chunk: [chunk][n=256][k=32] bf16, hi and lo parts.
#define WCHUNK_BYTES 16384
__device__ __align__(16) unsigned char g_w_hi[NCHUNK * WCHUNK_BYTES];
__device__ __align__(16) unsigned char g_w_lo[NCHUNK * WCHUNK_BYTES];
__device__ __align__(16) uchar2 g_pairs[NIN];   // {i, j}; j==255 => linear channel

// ---------------- smem layout (dynamic) ----------------
// XS : x tile   [64 ch][128 px] fp32                  = 32768 B
// YS : Y tiles  [hi|lo][128 px][stride 80B] bf16      = 20480 B
// WS : W tiles  [hi|lo][256 n ][stride 80B] bf16      = 40960 B
// PS : pair table 2144 uchar2                          =  4352 B
// Epilogue reuses [0, 34816) as fp32 [64][136] buffer.
#define SM_XS   0
#define SM_YS   32768
#define SM_WS   53248
#define SM_PS   94208
#define SM_TOT  98560

// ---------------- asm helpers ----------------
__device__ __forceinline__ void ldsm4(uint32_t (&r)[4], uint32_t addr) {
    asm volatile("ldmatrix.sync.aligned.m8n8.x4.shared.b16 {%0,%1,%2,%3}, [%4];"
                 : "=r"(r[0]), "=r"(r[1]), "=r"(r[2]), "=r"(r[3]) : "r"(addr));
}
__device__ __forceinline__ void mma16816(float (&c)[4], const uint32_t (&a)[4],
                                         uint32_t b0, uint32_t b1) {
    asm volatile(
        "mma.sync.aligned.m16n8k16.row.col.f32.bf16.bf16.f32 "
        "{%0,%1,%2,%3}, {%4,%5,%6,%7}, {%8,%9}, {%0,%1,%2,%3};"
        : "+f"(c[0]), "+f"(c[1]), "+f"(c[2]), "+f"(c[3])
        : "r"(a[0]), "r"(a[1]), "r"(a[2]), "r"(a[3]), "r"(b0), "r"(b1));
}

// ---------------- prep kernels ----------------
__global__ void init_pairs_kernel() {
    int i = threadIdx.x;
    if (i < C_CH) {
        g_pairs[i] = make_uchar2((unsigned char)i, 255);
        int base = C_CH + C_CH * i - (i * (i - 1)) / 2;
        for (int j = i; j < C_CH; j++)
            g_pairs[base + (j - i)] = make_uchar2((unsigned char)i, (unsigned char)j);
    }
}

__global__ void w_split_kernel(const float* __restrict__ w) {
    int c = blockIdx.x;              // chunk
    int n = threadIdx.x;             // output row 0..255
    const float* wr = w + (size_t)n * NIN + c * KC;
    uint32_t* hb = (uint32_t*)(g_w_hi + (size_t)c * WCHUNK_BYTES) + n * 16;
    uint32_t* lb = (uint32_t*)(g_w_lo + (size_t)c * WCHUNK_BYTES) + n * 16;
    #pragma unroll
    for (int kp = 0; kp < 16; kp++) {
        float f0 = wr[2 * kp], f1 = wr[2 * kp + 1];
        __nv_bfloat162 h2 = __float22bfloat162_rn(make_float2(f0, f1));
        float2 hf = __bfloat1622float2(h2);
        __nv_bfloat162 l2 = __float22bfloat162_rn(make_float2(f0 - hf.x, f1 - hf.y));
        hb[kp] = *(uint32_t*)&h2;
        lb[kp] = *(uint32_t*)&l2;
    }
}

// ---------------- main kernel ----------------
__global__ __launch_bounds__(NTH, 1)
void quad_hmma_kernel(const float* __restrict__ x, float* __restrict__ out) {
    extern __shared__ __align__(1024) unsigned char smem[];
    const int tid  = threadIdx.x;
    const int wid  = tid >> 5;
    const int lane = tid & 31;
    const int wm   = wid >> 2;          // warp row (M): 0..3, 32 px each
    const int wn   = wid & 3;           // warp col (N): 0..3, 64 ch each
    const uint32_t sb = (uint32_t)__cvta_generic_to_shared(smem);

    float*  xs = (float*)(smem + SM_XS);
    uchar2* ps = (uchar2*)(smem + SM_PS);

    // ---- global pixel tile ----
    const int p0  = blockIdx.x * PX_CTA;
    const int b   = p0 >> 12;
    const int hw0 = p0 & 4095;
    const float* xb = x + (((size_t)b * C_CH) << 12) + hw0;

    // ---- load x tile: 64 ch x 128 px (2048 float4, 4/thread) ----
    #pragma unroll
    for (int t = 0; t < 4; t++) {
        int e  = tid + t * NTH;
        int ch = e >> 5;
        int po = (e & 31) << 2;
        *(float4*)(xs + ch * 128 + po) = *(const float4*)(xb + ((size_t)ch << 12) + po);
    }
    // ---- load pair table (268 uint4) ----
    if (tid < 268) ((uint4*)ps)[tid] = ((const uint4*)g_pairs)[tid];
    __syncthreads();

    // ---- per-lane ldmatrix address offsets ----
    const uint32_t aoff = (uint32_t)((wm * 32 + (lane & 15)) * 80 + ((lane >> 4) & 1) * 16);
    const uint32_t boff = (uint32_t)((wn * 64 + ((lane >> 4) << 3) + (lane & 7)) * 80
                                     + ((lane >> 3) & 1) * 16);
    const uint32_t ysb = sb + SM_YS;
    const uint32_t wsb = sb + SM_WS;

    float acc[2][8][4];
    #pragma unroll
    for (int mt = 0; mt < 2; mt++)
        #pragma unroll
        for (int j = 0; j < 8; j++)
            #pragma unroll
            for (int q = 0; q < 4; q++) acc[mt][j][q] = 0.0f;

    const int pY = tid & 127;           // pixel this thread builds
    const int kg = (tid >> 7) * 2;      // k-pair group

    for (int c = 0; c < NCHUNK; c++) {
        __syncthreads();   // previous chunk's ldmatrix reads complete

        // ---- copy W chunk hi+lo into padded smem (4 uint4/thread) ----
        {
            const uint4* srch = (const uint4*)(g_w_hi + (size_t)c * WCHUNK_BYTES);
            const uint4* srcl = (const uint4*)(g_w_lo + (size_t)c * WCHUNK_BYTES);
            #pragma unroll
            for (int t = 0; t < 2; t++) {
                int u  = tid + t * NTH;      // 0..1023
                int n  = u >> 2;
                int kq = u & 3;
                *(uint4*)(smem + SM_WS +         n * 80 + kq * 16) = srch[u];
                *(uint4*)(smem + SM_WS + 20480 + n * 80 + kq * 16) = srcl[u];
            }
        }

        // ---- build Y hi/lo: this thread covers (pY, k = t*8+kg, +1) ----
        {
            const uchar2* pc = ps + c * KC;
            #pragma unroll
            for (int t = 0; t < 4; t++) {
                int k0 = t * 8 + kg;
                uchar2 e0 = pc[k0], e1 = pc[k0 + 1];
                int j0 = (e0.y == 255) ? e0.x : e0.y;
                int j1 = (e1.y == 255) ? e1.x : e1.y;
                float xj0 = xs[j0 * 128 + pY];
                float xj1 = xs[j1 * 128 + pY];
                float y0 = xs[e0.x * 128 + pY] * ((e0.y == 255) ? 1.0f : xj0);
                float y1 = xs[e1.x * 128 + pY] * ((e1.y == 255) ? 1.0f : xj1);
                __nv_bfloat162 h2 = __float22bfloat162_rn(make_float2(y0, y1));
                float2 hf = __bfloat1622float2(h2);
                __nv_bfloat162 l2 = __float22bfloat162_rn(make_float2(y0 - hf.x, y1 - hf.y));
                *(uint32_t*)(smem + SM_YS +         pY * 80 + k0 * 2) = *(uint32_t*)&h2;
                *(uint32_t*)(smem + SM_YS + 10240 + pY * 80 + k0 * 2) = *(uint32_t*)&l2;
            }
        }
        __syncthreads();

        // ---- MMAs: 2 k16 slices x (hi*hi + lo*hi + hi*lo) ----
        #pragma unroll
        for (int ks = 0; ks < 2; ks++) {
            uint32_t ah[2][4], al[2][4], bb[4][4];
            #pragma unroll
            for (int mt = 0; mt < 2; mt++) {
                ldsm4(ah[mt], ysb +         mt * 1280 + ks * 32 + aoff);
                ldsm4(al[mt], ysb + 10240 + mt * 1280 + ks * 32 + aoff);
            }
            #pragma unroll
            for (int nt = 0; nt < 4; nt++)
                ldsm4(bb[nt], wsb + nt * 1280 + ks * 32 + boff);          // W_hi
            #pragma unroll
            for (int mt = 0; mt < 2; mt++)
                #pragma unroll
                for (int j = 0; j < 8; j++)
                    mma16816(acc[mt][j], ah[mt], bb[j >> 1][(j & 1) * 2],
                             bb[j >> 1][(j & 1) * 2 + 1]);
            #pragma unroll
            for (int mt = 0; mt < 2; mt++)
                #pragma unroll
                for (int j = 0; j < 8; j++)
                    mma16816(acc[mt][j], al[mt], bb[j >> 1][(j & 1) * 2],
                             bb[j >> 1][(j & 1) * 2 + 1]);
            #pragma unroll
            for (int nt = 0; nt < 4; nt++)
                ldsm4(bb[nt], wsb + 20480 + nt * 1280 + ks * 32 + boff);  // W_lo
            #pragma unroll
            for (int mt = 0; mt < 2; mt++)
                #pragma unroll
                for (int j = 0; j < 8; j++)
                    mma16816(acc[mt][j], ah[mt], bb[j >> 1][(j & 1) * 2],
                             bb[j >> 1][(j & 1) * 2 + 1]);
        }
    }

    // ---- epilogue: transpose via smem, coalesced stores ----
    float* buf = (float*)smem;                       // [64][136] fp32
    float* ob  = out + ((size_t)b * OUT_CH) * HW + hw0;
    #pragma unroll 1
    for (int slab = 0; slab < 4; slab++) {
        __syncthreads();
        if (wn == slab) {
            #pragma unroll
            for (int mt = 0; mt < 2; mt++)
                #pragma unroll
                for (int j = 0; j < 8; j++) {
                    int px = wm * 32 + mt * 16 + (lane >> 2);
                    int ch = j * 8 + (lane & 3) * 2;
                    buf[ch * 136 + px]           = acc[mt][j][0];
                    buf[(ch + 1) * 136 + px]     = acc[mt][j][1];
                    buf[ch * 136 + px + 8]       = acc[mt][j][2];
                    buf[(ch + 1) * 136 + px + 8] = acc[mt][j][3];
                }
        }
        __syncthreads();
        #pragma unroll
        for (int t = 0; t < 4; t++) {
            int e   = tid + t * NTH;                 // 0..2047
            int chl = e >> 5;
            int po  = (e & 31) << 2;
            float4 v = *(float4*)(buf + chl * 136 + po);
            *(float4*)(ob + (size_t)(slab * 64 + chl) * HW + po) = v;
        }
    }
}

// ---------------- launch ----------------
extern "C" void kernel_launch(void* const* d_in, const int* in_sizes, int n_in,
                              void* d_out, int out_size) {
    const float* x = (const float*)d_in[0];    // [B, 64, 64, 64] fp32
    const float* w = (const float*)d_in[1];    // [256, 2144] fp32
    float* out = (float*)d_out;                // [B, 256, 64, 64] fp32

    int pixels = in_sizes[0] / C_CH;           // B * 4096

    cudaFuncSetAttribute(quad_hmma_kernel,
                         cudaFuncAttributeMaxDynamicSharedMemorySize, SM_TOT);

    init_pairs_kernel<<<1, 64>>>();
    w_split_kernel<<<NCHUNK, 256>>>(w);
    quad_hmma_kernel<<<pixels / PX_CTA, NTH, SM_TOT>>>(x, out);
}

// round 4
// speedup vs baseline: 5.7715x; 1.5881x over previous
#include <cuda_runtime.h>
#include <cuda_fp16.h>
#include <cstdint>

#define C_CH     64
#define NIN      2144
#define OUT_CH   256
#define HW       4096
#define KC       32
#define NCHUNK   67          // 2144 / 32
#define PX_CTA   128
#define NTH      512

// ---------------- prep storage (device globals) ----------------
// Pre-split W per chunk: [chunk][n=256][k=32] fp16 (scaled by 64).
#define WCHUNK_BYTES 16384
__device__ __align__(16) unsigned char g_w[NCHUNK * WCHUNK_BYTES];
__device__ __align__(16) uchar2 g_pairs[NIN];   // {i, j}; j==255 => linear channel

// ---------------- smem layout (dynamic) ----------------
// XS : x tile [64 ch][128 px] fp32                       = 32768 B
// Y  : 2 stages x [hi|lo][128 px][stride 80B] fp16       = 2 x 20480 B
// W  : 2 stages x [256 n][stride 80B] fp16               = 2 x 20480 B
// PS : pair table 2144 uchar2                            =  4352 B
// Epilogue reuses [0, 34816) as fp32 [64][136] buffer.
#define SM_XS   0
#define SM_Y    32768
#define SM_W    73728
#define SM_PS   114688
#define SM_TOT  119040

#define Y_STAGE 20480
#define W_STAGE 20480

// ---------------- asm helpers ----------------
__device__ __forceinline__ void ldsm4(uint32_t (&r)[4], uint32_t addr) {
    asm volatile("ldmatrix.sync.aligned.m8n8.x4.shared.b16 {%0,%1,%2,%3}, [%4];"
                 : "=r"(r[0]), "=r"(r[1]), "=r"(r[2]), "=r"(r[3]) : "r"(addr));
}
__device__ __forceinline__ void mma16816(float (&c)[4], const uint32_t (&a)[4],
                                         uint32_t b0, uint32_t b1) {
    asm volatile(
        "mma.sync.aligned.m16n8k16.row.col.f32.f16.f16.f32 "
        "{%0,%1,%2,%3}, {%4,%5,%6,%7}, {%8,%9}, {%0,%1,%2,%3};"
        : "+f"(c[0]), "+f"(c[1]), "+f"(c[2]), "+f"(c[3])
        : "r"(a[0]), "r"(a[1]), "r"(a[2]), "r"(a[3]), "r"(b0), "r"(b1));
}
__device__ __forceinline__ void cp_async16(uint32_t saddr, const void* gptr) {
    asm volatile("cp.async.cg.shared.global [%0], [%1], 16;"
                 :: "r"(saddr), "l"(gptr) : "memory");
}

// ---------------- prep kernels ----------------
__global__ void init_pairs_kernel() {
    int i = threadIdx.x;
    if (i < C_CH) {
        g_pairs[i] = make_uchar2((unsigned char)i, 255);
        int base = C_CH + C_CH * i - (i * (i - 1)) / 2;
        for (int j = i; j < C_CH; j++)
            g_pairs[base + (j - i)] = make_uchar2((unsigned char)i, (unsigned char)j);
    }
}

__global__ void w_split_kernel(const float* __restrict__ w) {
    int c = blockIdx.x;              // chunk
    int n = threadIdx.x;             // output row 0..255
    const float* wr = w + (size_t)n * NIN + c * KC;
    uint32_t* wb = (uint32_t*)(g_w + (size_t)c * WCHUNK_BYTES) + n * 16;
    #pragma unroll
    for (int kp = 0; kp < 16; kp++) {
        __half2 h2 = __float22half2_rn(
            make_float2(64.0f * wr[2 * kp], 64.0f * wr[2 * kp + 1]));
        wb[kp] = *(uint32_t*)&h2;
    }
}

// ---------------- main kernel ----------------
__global__ __launch_bounds__(NTH, 1)
void quad_hmma_kernel(const float* __restrict__ x, float* __restrict__ out) {
    extern __shared__ __align__(1024) unsigned char smem[];
    const int tid  = threadIdx.x;
    const int wid  = tid >> 5;
    const int lane = tid & 31;
    const int wm   = wid >> 2;          // warp row (M): 0..3, 32 px each
    const int wn   = wid & 3;           // warp col (N): 0..3, 64 ch each
    const uint32_t sb = (uint32_t)__cvta_generic_to_shared(smem);

    float*  xs = (float*)(smem + SM_XS);
    uchar2* ps = (uchar2*)(smem + SM_PS);

    // ---- global pixel tile ----
    const int p0  = blockIdx.x * PX_CTA;
    const int b   = p0 >> 12;
    const int hw0 = p0 & 4095;
    const float* xb = x + (((size_t)b * C_CH) << 12) + hw0;

    // ---- load x tile: 64 ch x 128 px (2048 float4, 4/thread) ----
    #pragma unroll
    for (int t = 0; t < 4; t++) {
        int e  = tid + t * NTH;
        int ch = e >> 5;
        int po = (e & 31) << 2;
        *(float4*)(xs + ch * 128 + po) = *(const float4*)(xb + ((size_t)ch << 12) + po);
    }
    if (tid < 268) ((uint4*)ps)[tid] = ((const uint4*)g_pairs)[tid];
    __syncthreads();

    // ---- per-lane ldmatrix offsets ----
    const uint32_t aoff = (uint32_t)((wm * 32 + (lane & 15)) * 80 + ((lane >> 4) & 1) * 16);
    const uint32_t boff = (uint32_t)((wn * 64 + ((lane >> 4) << 3) + (lane & 7)) * 80
                                     + ((lane >> 3) & 1) * 16);
    const uint32_t ysb = sb + SM_Y;
    const uint32_t wsb = sb + SM_W;

    float acc[2][8][4];
    #pragma unroll
    for (int mt = 0; mt < 2; mt++)
        #pragma unroll
        for (int j = 0; j < 8; j++)
            #pragma unroll
            for (int q = 0; q < 4; q++) acc[mt][j][q] = 0.0f;

    const int pY = tid & 127;           // pixel this thread builds
    const int kg = (tid >> 7) * 2;      // k-pair group

    // ---- copy W chunk c into stage via cp.async (2 x 16B per thread) ----
    auto copyW = [&](int c, int stage) {
        const unsigned char* src = g_w + (size_t)c * WCHUNK_BYTES;
        #pragma unroll
        for (int t = 0; t < 2; t++) {
            int u  = tid + t * NTH;      // 0..1023
            int n  = u >> 2;
            int kq = u & 3;
            cp_async16(sb + SM_W + stage * W_STAGE + n * 80 + kq * 16,
                       src + n * 64 + kq * 16);
        }
        asm volatile("cp.async.commit_group;" ::: "memory");
    };

    // ---- build Y chunk c (hi/lo fp16, scaled by 64) into stage ----
    auto buildY = [&](int c, int stage) {
        const uchar2* pc = ps + c * KC;
        unsigned char* ybase = smem + SM_Y + stage * Y_STAGE;
        #pragma unroll
        for (int t = 0; t < 4; t++) {
            int k0 = t * 8 + kg;
            uchar2 e0 = pc[k0], e1 = pc[k0 + 1];
            float y0 = 64.0f * xs[e0.x * 128 + pY] *
                       ((e0.y == 255) ? 1.0f : xs[e0.y * 128 + pY]);
            float y1 = 64.0f * xs[e1.x * 128 + pY] *
                       ((e1.y == 255) ? 1.0f : xs[e1.y * 128 + pY]);
            __half2 h2 = __float22half2_rn(make_float2(y0, y1));
            float2 hf = __half22float2(h2);
            __half2 l2 = __float22half2_rn(make_float2(y0 - hf.x, y1 - hf.y));
            *(uint32_t*)(ybase +         pY * 80 + k0 * 2) = *(uint32_t*)&h2;
            *(uint32_t*)(ybase + 10240 + pY * 80 + k0 * 2) = *(uint32_t*)&l2;
        }
    };

    // ---- prologue: stage 0 ----
    copyW(0, 0);
    buildY(0, 0);
    asm volatile("cp.async.wait_group 0;" ::: "memory");
    __syncthreads();

    for (int c = 0; c < NCHUNK; c++) {
        const int cur = c & 1;
        const int nxt = cur ^ 1;

        if (c + 1 < NCHUNK) copyW(c + 1, nxt);

        // ---- MMAs for chunk c: 2 k-slices x (y_hi + y_lo) x W ----
        const uint32_t ycur = ysb + cur * Y_STAGE;
        const uint32_t wcur = wsb + cur * W_STAGE;
        #pragma unroll
        for (int ks = 0; ks < 2; ks++) {
            uint32_t ah[2][4], al[2][4], bb[4][4];
            #pragma unroll
            for (int mt = 0; mt < 2; mt++) {
                ldsm4(ah[mt], ycur +         mt * 1280 + ks * 32 + aoff);
                ldsm4(al[mt], ycur + 10240 + mt * 1280 + ks * 32 + aoff);
            }
            #pragma unroll
            for (int nt = 0; nt < 4; nt++)
                ldsm4(bb[nt], wcur + nt * 1280 + ks * 32 + boff);
            #pragma unroll
            for (int mt = 0; mt < 2; mt++)
                #pragma unroll
                for (int j = 0; j < 8; j++)
                    mma16816(acc[mt][j], ah[mt], bb[j >> 1][(j & 1) * 2],
                             bb[j >> 1][(j & 1) * 2 + 1]);
            #pragma unroll
            for (int mt = 0; mt < 2; mt++)
                #pragma unroll
                for (int j = 0; j < 8; j++)
                    mma16816(acc[mt][j], al[mt], bb[j >> 1][(j & 1) * 2],
                             bb[j >> 1][(j & 1) * 2 + 1]);
        }

        if (c + 1 < NCHUNK) buildY(c + 1, nxt);

        asm volatile("cp.async.wait_group 0;" ::: "memory");
        __syncthreads();
    }

    // ---- epilogue: transpose via smem, coalesced stores, undo 64*64 scale ----
    const float inv = 1.0f / 4096.0f;
    float* buf = (float*)smem;                       // [64][136] fp32
    float* ob  = out + ((size_t)b * OUT_CH) * HW + hw0;
    #pragma unroll 1
    for (int slab = 0; slab < 4; slab++) {
        __syncthreads();
        if (wn == slab) {
            #pragma unroll
            for (int mt = 0; mt < 2; mt++)
                #pragma unroll
                for (int j = 0; j < 8; j++) {
                    int px = wm * 32 + mt * 16 + (lane >> 2);
                    int ch = j * 8 + (lane & 3) * 2;
                    buf[ch * 136 + px]           = acc[mt][j][0] * inv;
                    buf[(ch + 1) * 136 + px]     = acc[mt][j][1] * inv;
                    buf[ch * 136 + px + 8]       = acc[mt][j][2] * inv;
                    buf[(ch + 1) * 136 + px + 8] = acc[mt][j][3] * inv;
                }
        }
        __syncthreads();
        #pragma unroll
        for (int t = 0; t < 4; t++) {
            int e   = tid + t * NTH;                 // 0..2047
            int chl = e >> 5;
            int po  = (e & 31) << 2;
            float4 v = *(float4*)(buf + chl * 136 + po);
            *(float4*)(ob + (size_t)(slab * 64 + chl) * HW + po) = v;
        }
    }
}

// ---------------- launch ----------------
extern "C" void kernel_launch(void* const* d_in, const int* in_sizes, int n_in,
                              void* d_out, int out_size) {
    const float* x = (const float*)d_in[0];    // [B, 64, 64, 64] fp32
    const float* w = (const float*)d_in[1];    // [256, 2144] fp32
    float* out = (float*)d_out;                // [B, 256, 64, 64] fp32

    int pixels = in_sizes[0] / C_CH;           // B * 4096

    cudaFuncSetAttribute(quad_hmma_kernel,
                         cudaFuncAttributeMaxDynamicSharedMemorySize, SM_TOT);

    init_pairs_kernel<<<1, 64>>>();
    w_split_kernel<<<NCHUNK, 256>>>(w);
    quad_hmma_kernel<<<pixels / PX_CTA, NTH, SM_TOT>>>(x, out);
}

// round 5
// speedup vs baseline: 8.8308x; 1.5301x over previous
#include <cuda_runtime.h>
#include <cuda_fp16.h>
#include <cstdint>

#define C_CH     64
#define NIN      2144
#define OUT_CH   256
#define HW       4096
#define KC       32
#define NCHUNK   67          // 2144 / 32
#define PX_CTA   128
#define NTH      512

// ---------------- prep storage (device globals) ----------------
// W per chunk: [chunk][n=256][k=32] fp16 (scaled by 64).
#define WCHUNK_BYTES 16384
__device__ __align__(16) unsigned char g_w[NCHUNK * WCHUNK_BYTES];
__device__ __align__(16) uchar2 g_pairs[NIN];   // {i, j}; j==255 => linear channel

// ---------------- smem layout (dynamic) ----------------
// XS : x tile [64 ch][128 px] fp32                 = 32768 B
// Y  : 2 stages x [128 px][stride 80B] fp16        = 2 x 10240 B
// W  : 2 stages x [256 n][stride 80B] fp16         = 2 x 20480 B
// PS : pair table 2144 uchar2                      =  4352 B
// Epilogue reuses [0, 34816) as fp32 [64][136] buffer.
#define SM_XS   0
#define SM_Y    32768
#define SM_W    53248
#define SM_PS   94208
#define SM_TOT  98560

#define Y_STAGE 10240
#define W_STAGE 20480

// ---------------- asm helpers ----------------
__device__ __forceinline__ void ldsm4(uint32_t (&r)[4], uint32_t addr) {
    asm volatile("ldmatrix.sync.aligned.m8n8.x4.shared.b16 {%0,%1,%2,%3}, [%4];"
                 : "=r"(r[0]), "=r"(r[1]), "=r"(r[2]), "=r"(r[3]) : "r"(addr));
}
__device__ __forceinline__ void mma16816(float (&c)[4], const uint32_t (&a)[4],
                                         uint32_t b0, uint32_t b1) {
    asm volatile(
        "mma.sync.aligned.m16n8k16.row.col.f32.f16.f16.f32 "
        "{%0,%1,%2,%3}, {%4,%5,%6,%7}, {%8,%9}, {%0,%1,%2,%3};"
        : "+f"(c[0]), "+f"(c[1]), "+f"(c[2]), "+f"(c[3])
        : "r"(a[0]), "r"(a[1]), "r"(a[2]), "r"(a[3]), "r"(b0), "r"(b1));
}
__device__ __forceinline__ void cp_async16(uint32_t saddr, const void* gptr) {
    asm volatile("cp.async.cg.shared.global [%0], [%1], 16;"
                 :: "r"(saddr), "l"(gptr) : "memory");
}

// ---------------- prep kernel (pairs + W convert, one launch) ----------------
__global__ void w_prep_kernel(const float* __restrict__ w) {
    int c = blockIdx.x;              // chunk
    int n = threadIdx.x;             // output row 0..255

    if (c == 0 && n < C_CH) {        // pair table (block 0 only)
        int i = n;
        g_pairs[i] = make_uchar2((unsigned char)i, 255);
        int base = C_CH + C_CH * i - (i * (i - 1)) / 2;
        for (int j = i; j < C_CH; j++)
            g_pairs[base + (j - i)] = make_uchar2((unsigned char)i, (unsigned char)j);
    }

    const float* wr = w + (size_t)n * NIN + c * KC;
    uint32_t* wb = (uint32_t*)(g_w + (size_t)c * WCHUNK_BYTES) + n * 16;
    #pragma unroll
    for (int kp = 0; kp < 16; kp++) {
        __half2 h2 = __float22half2_rn(
            make_float2(64.0f * wr[2 * kp], 64.0f * wr[2 * kp + 1]));
        wb[kp] = *(uint32_t*)&h2;
    }
}

// ---------------- main kernel ----------------
__global__ __launch_bounds__(NTH, 1)
void quad_hmma_kernel(const float* __restrict__ x, float* __restrict__ out) {
    extern __shared__ __align__(1024) unsigned char smem[];
    const int tid  = threadIdx.x;
    const int wid  = tid >> 5;
    const int lane = tid & 31;
    const int wm   = wid >> 2;          // warp row (M): 0..3, 32 px each
    const int wn   = wid & 3;           // warp col (N): 0..3, 64 ch each
    const uint32_t sb = (uint32_t)__cvta_generic_to_shared(smem);

    float*  xs = (float*)(smem + SM_XS);
    uchar2* ps = (uchar2*)(smem + SM_PS);

    // ---- global pixel tile ----
    const int p0  = blockIdx.x * PX_CTA;
    const int b   = p0 >> 12;
    const int hw0 = p0 & 4095;
    const float* xb = x + (((size_t)b * C_CH) << 12) + hw0;

    // ---- load x tile: 64 ch x 128 px (2048 float4, 4/thread) ----
    #pragma unroll
    for (int t = 0; t < 4; t++) {
        int e  = tid + t * NTH;
        int ch = e >> 5;
        int po = (e & 31) << 2;
        *(float4*)(xs + ch * 128 + po) = *(const float4*)(xb + ((size_t)ch << 12) + po);
    }
    if (tid < 268) ((uint4*)ps)[tid] = ((const uint4*)g_pairs)[tid];
    __syncthreads();

    // ---- per-lane ldmatrix offsets ----
    const uint32_t aoff = (uint32_t)((wm * 32 + (lane & 15)) * 80 + ((lane >> 4) & 1) * 16);
    const uint32_t boff = (uint32_t)((wn * 64 + ((lane >> 4) << 3) + (lane & 7)) * 80
                                     + ((lane >> 3) & 1) * 16);
    const uint32_t ysb = sb + SM_Y;
    const uint32_t wsb = sb + SM_W;

    float acc[2][8][4];
    #pragma unroll
    for (int mt = 0; mt < 2; mt++)
        #pragma unroll
        for (int j = 0; j < 8; j++)
            #pragma unroll
            for (int q = 0; q < 4; q++) acc[mt][j][q] = 0.0f;

    const int pY = tid & 127;           // pixel this thread builds
    const int kg = (tid >> 7) * 2;      // k-pair group

    // ---- copy W chunk c into stage via cp.async (2 x 16B per thread) ----
    auto copyW = [&](int c, int stage) {
        const unsigned char* src = g_w + (size_t)c * WCHUNK_BYTES;
        #pragma unroll
        for (int t = 0; t < 2; t++) {
            int u  = tid + t * NTH;      // 0..1023
            int n  = u >> 2;
            int kq = u & 3;
            cp_async16(sb + SM_W + stage * W_STAGE + n * 80 + kq * 16,
                       src + n * 64 + kq * 16);
        }
        asm volatile("cp.async.commit_group;" ::: "memory");
    };

    // ---- build Y chunk c (fp16, scaled by 64) into stage ----
    auto buildY = [&](int c, int stage) {
        const uchar2* pc = ps + c * KC;
        unsigned char* ybase = smem + SM_Y + stage * Y_STAGE;
        #pragma unroll
        for (int t = 0; t < 4; t++) {
            int k0 = t * 8 + kg;
            uchar2 e0 = pc[k0], e1 = pc[k0 + 1];
            float y0 = 64.0f * xs[e0.x * 128 + pY] *
                       ((e0.y == 255) ? 1.0f : xs[e0.y * 128 + pY]);
            float y1 = 64.0f * xs[e1.x * 128 + pY] *
                       ((e1.y == 255) ? 1.0f : xs[e1.y * 128 + pY]);
            __half2 h2 = __float22half2_rn(make_float2(y0, y1));
            *(uint32_t*)(ybase + pY * 80 + k0 * 2) = *(uint32_t*)&h2;
        }
    };

    // ---- prologue: stage 0 ----
    copyW(0, 0);
    buildY(0, 0);
    asm volatile("cp.async.wait_group 0;" ::: "memory");
    __syncthreads();

    for (int c = 0; c < NCHUNK; c++) {
        const int cur = c & 1;
        const int nxt = cur ^ 1;

        if (c + 1 < NCHUNK) copyW(c + 1, nxt);

        // ---- MMAs for chunk c: 2 k-slices ----
        const uint32_t ycur = ysb + cur * Y_STAGE;
        const uint32_t wcur = wsb + cur * W_STAGE;
        #pragma unroll
        for (int ks = 0; ks < 2; ks++) {
            uint32_t ah[2][4], bb[4][4];
            #pragma unroll
            for (int mt = 0; mt < 2; mt++)
                ldsm4(ah[mt], ycur + mt * 1280 + ks * 32 + aoff);
            #pragma unroll
            for (int nt = 0; nt < 4; nt++)
                ldsm4(bb[nt], wcur + nt * 1280 + ks * 32 + boff);
            #pragma unroll
            for (int mt = 0; mt < 2; mt++)
                #pragma unroll
                for (int j = 0; j < 8; j++)
                    mma16816(acc[mt][j], ah[mt], bb[j >> 1][(j & 1) * 2],
                             bb[j >> 1][(j & 1) * 2 + 1]);
        }

        if (c + 1 < NCHUNK) buildY(c + 1, nxt);

        asm volatile("cp.async.wait_group 0;" ::: "memory");
        __syncthreads();
    }

    // ---- epilogue: transpose via smem, coalesced stores, undo 64*64 scale ----
    const float inv = 1.0f / 4096.0f;
    float* buf = (float*)smem;                       // [64][136] fp32
    float* ob  = out + ((size_t)b * OUT_CH) * HW + hw0;
    #pragma unroll 1
    for (int slab = 0; slab < 4; slab++) {
        __syncthreads();
        if (wn == slab) {
            #pragma unroll
            for (int mt = 0; mt < 2; mt++)
                #pragma unroll
                for (int j = 0; j < 8; j++) {
                    int px = wm * 32 + mt * 16 + (lane >> 2);
                    int ch = j * 8 + (lane & 3) * 2;
                    buf[ch * 136 + px]           = acc[mt][j][0] * inv;
                    buf[(ch + 1) * 136 + px]     = acc[mt][j][1] * inv;
                    buf[ch * 136 + px + 8]       = acc[mt][j][2] * inv;
                    buf[(ch + 1) * 136 + px + 8] = acc[mt][j][3] * inv;
                }
        }
        __syncthreads();
        #pragma unroll
        for (int t = 0; t < 4; t++) {
            int e   = tid + t * NTH;                 // 0..2047
            int chl = e >> 5;
            int po  = (e & 31) << 2;
            float4 v = *(float4*)(buf + chl * 136 + po);
            *(float4*)(ob + (size_t)(slab * 64 + chl) * HW + po) = v;
        }
    }
}

// ---------------- launch ----------------
extern "C" void kernel_launch(void* const* d_in, const int* in_sizes, int n_in,
                              void* d_out, int out_size) {
    const float* x = (const float*)d_in[0];    // [B, 64, 64, 64] fp32
    const float* w = (const float*)d_in[1];    // [256, 2144] fp32
    float* out = (float*)d_out;                // [B, 256, 64, 64] fp32

    int pixels = in_sizes[0] / C_CH;           // B * 4096

    cudaFuncSetAttribute(quad_hmma_kernel,
                         cudaFuncAttributeMaxDynamicSharedMemorySize, SM_TOT);

    w_prep_kernel<<<NCHUNK, 256>>>(w);
    quad_hmma_kernel<<<pixels / PX_CTA, NTH, SM_TOT>>>(x, out);
}

// round 6
// speedup vs baseline: 8.8378x; 1.0008x over previous
#include <cuda_runtime.h>
#include <cuda_fp16.h>
#include <cstdint>

#define C_CH     64
#define NIN      2144
#define NINP     2176        // padded to 34*64
#define OUT_CH   256
#define HW       4096
#define KC       64
#define NCHUNK   34
#define PX_CTA   128
#define NTH      512

// ---------------- prep storage (device globals) ----------------
// W per chunk: [chunk][n=256][k=64] fp16 (scaled by 64, zero-padded past 2144).
#define WCHUNK_BYTES 32768
__device__ __align__(16) unsigned char g_w[NCHUNK * WCHUNK_BYTES];
__device__ __align__(16) uchar2 g_pairs[NINP];   // {i, j}; j==255 => linear channel

// ---------------- smem layout (dynamic) ----------------
// XS : x tile [64 ch][128 px] fp32             = 32768 B
// Y  : 2 stages x [128 px][stride 144B] fp16   = 2 x 18432 B
// W  : 2 stages x [256 n ][stride 144B] fp16   = 2 x 36864 B
// PS : pair table 2176 uchar2                  =  4352 B
// Epilogue reuses [0, 34816) as fp32 [64][136] buffer.
#define SM_XS    0
#define SM_Y     32768
#define Y_STAGE  18432
#define SM_W     69632
#define W_STAGE  36864
#define SM_PS    143360
#define SM_TOT   147712

// ---------------- asm helpers ----------------
__device__ __forceinline__ void ldsm4(uint32_t (&r)[4], uint32_t addr) {
    asm volatile("ldmatrix.sync.aligned.m8n8.x4.shared.b16 {%0,%1,%2,%3}, [%4];"
                 : "=r"(r[0]), "=r"(r[1]), "=r"(r[2]), "=r"(r[3]) : "r"(addr));
}
__device__ __forceinline__ void mma16816(float (&c)[4], const uint32_t (&a)[4],
                                         uint32_t b0, uint32_t b1) {
    asm volatile(
        "mma.sync.aligned.m16n8k16.row.col.f32.f16.f16.f32 "
        "{%0,%1,%2,%3}, {%4,%5,%6,%7}, {%8,%9}, {%0,%1,%2,%3};"
        : "+f"(c[0]), "+f"(c[1]), "+f"(c[2]), "+f"(c[3])
        : "r"(a[0]), "r"(a[1]), "r"(a[2]), "r"(a[3]), "r"(b0), "r"(b1));
}
__device__ __forceinline__ void cp_async16(uint32_t saddr, const void* gptr) {
    asm volatile("cp.async.cg.shared.global [%0], [%1], 16;"
                 :: "r"(saddr), "l"(gptr) : "memory");
}

// ---------------- prep kernel (pairs + W convert, one launch) ----------------
__global__ void w_prep_kernel(const float* __restrict__ w) {
    int c = blockIdx.x;              // chunk 0..33
    int n = threadIdx.x;             // output row 0..255

    if (c == 0 && n < C_CH) {        // pair table
        int i = n;
        g_pairs[i] = make_uchar2((unsigned char)i, 255);
        int base = C_CH + C_CH * i - (i * (i - 1)) / 2;
        for (int j = i; j < C_CH; j++)
            g_pairs[base + (j - i)] = make_uchar2((unsigned char)i, (unsigned char)j);
    }
    if (c == 0 && n >= 64 && n < 96)             // padding pairs (W is zero there)
        g_pairs[NIN + (n - 64)] = make_uchar2(0, 0);

    const float* wr = w + (size_t)n * NIN;
    uint32_t* wb = (uint32_t*)(g_w + (size_t)c * WCHUNK_BYTES) + n * 32;
    #pragma unroll
    for (int kp = 0; kp < 32; kp++) {
        int k = c * KC + 2 * kp;
        float f0 = (k     < NIN) ? 64.0f * wr[k]     : 0.0f;
        float f1 = (k + 1 < NIN) ? 64.0f * wr[k + 1] : 0.0f;
        __half2 h2 = __float22half2_rn(make_float2(f0, f1));
        wb[kp] = *(uint32_t*)&h2;
    }
}

// ---------------- main kernel ----------------
__global__ __launch_bounds__(NTH, 1)
void quad_hmma_kernel(const float* __restrict__ x, float* __restrict__ out) {
    extern __shared__ __align__(1024) unsigned char smem[];
    const int tid  = threadIdx.x;
    const int wid  = tid >> 5;
    const int lane = tid & 31;
    const int wm   = wid >> 2;          // warp row (M): 0..3, 32 px each
    const int wn   = wid & 3;           // warp col (N): 0..3, 64 ch each
    const uint32_t sb = (uint32_t)__cvta_generic_to_shared(smem);

    float*  xs = (float*)(smem + SM_XS);
    uchar2* ps = (uchar2*)(smem + SM_PS);

    // ---- global pixel tile ----
    const int p0  = blockIdx.x * PX_CTA;
    const int b   = p0 >> 12;
    const int hw0 = p0 & 4095;
    const float* xb = x + (((size_t)b * C_CH) << 12) + hw0;

    // ---- load x tile: 64 ch x 128 px (2048 float4, 4/thread) ----
    #pragma unroll
    for (int t = 0; t < 4; t++) {
        int e  = tid + t * NTH;
        int ch = e >> 5;
        int po = (e & 31) << 2;
        *(float4*)(xs + ch * 128 + po) = *(const float4*)(xb + ((size_t)ch << 12) + po);
    }
    if (tid < NINP / 8) ((uint4*)ps)[tid] = ((const uint4*)g_pairs)[tid];
    __syncthreads();

    // ---- per-lane ldmatrix offsets (stride 144B rows, conflict-free) ----
    const uint32_t aoff = (uint32_t)((wm * 32 + (lane & 15)) * 144 + ((lane >> 4) & 1) * 16);
    const uint32_t boff = (uint32_t)((wn * 64 + ((lane >> 4) << 3) + (lane & 7)) * 144
                                     + ((lane >> 3) & 1) * 16);
    const uint32_t ysb = sb + SM_Y;
    const uint32_t wsb = sb + SM_W;

    float acc[2][8][4];
    #pragma unroll
    for (int mt = 0; mt < 2; mt++)
        #pragma unroll
        for (int j = 0; j < 8; j++)
            #pragma unroll
            for (int q = 0; q < 4; q++) acc[mt][j][q] = 0.0f;

    // ---- copy W chunk into stage via cp.async (4 x 16B per thread) ----
    auto copyW = [&](int c, int stage) {
        const unsigned char* src = g_w + (size_t)c * WCHUNK_BYTES;
        uint32_t dst = sb + SM_W + stage * W_STAGE;
        #pragma unroll
        for (int t = 0; t < 4; t++) {
            int u = tid + t * NTH;       // 0..2047
            int n = u >> 3;
            int q = u & 7;
            cp_async16(dst + n * 144 + q * 16, src + n * 128 + q * 16);
        }
        asm volatile("cp.async.commit_group;" ::: "memory");
    };

    // ---- build Y chunk (fp16, scaled 64): 16 k per thread, 2x STS.128 ----
    auto buildY = [&](int c, int stage) {
        const uchar2* pc = ps + c * KC + (tid >> 7) * 16;
        unsigned char* yb = smem + SM_Y + stage * Y_STAGE
                          + (tid & 127) * 144 + (tid >> 7) * 32;
        const float* xcol = xs + (tid & 127);
        uint32_t r[8];
        #pragma unroll
        for (int q = 0; q < 8; q++) {
            uchar2 e0 = pc[2 * q], e1 = pc[2 * q + 1];
            float y0 = 64.0f * xcol[e0.x * 128] *
                       ((e0.y == 255) ? 1.0f : xcol[e0.y * 128]);
            float y1 = 64.0f * xcol[e1.x * 128] *
                       ((e1.y == 255) ? 1.0f : xcol[e1.y * 128]);
            __half2 h2 = __float22half2_rn(make_float2(y0, y1));
            r[q] = *(uint32_t*)&h2;
        }
        *(uint4*)yb        = make_uint4(r[0], r[1], r[2], r[3]);
        *(uint4*)(yb + 16) = make_uint4(r[4], r[5], r[6], r[7]);
    };

    // ---- prologue: stage 0 ----
    copyW(0, 0);
    buildY(0, 0);
    asm volatile("cp.async.wait_group 0;" ::: "memory");
    __syncthreads();

    for (int c = 0; c < NCHUNK; c++) {
        const int cur = c & 1;
        const int nxt = cur ^ 1;
        const uint32_t ycur = ysb + cur * Y_STAGE;
        const uint32_t wcur = wsb + cur * W_STAGE;

        uint32_t aF[2][2][4], bF[2][4][4];
        // prefetch slice 0 fragments immediately after barrier
        #pragma unroll
        for (int mt = 0; mt < 2; mt++) ldsm4(aF[0][mt], ycur + mt * 2304 + aoff);
        #pragma unroll
        for (int nt = 0; nt < 4; nt++) ldsm4(bF[0][nt], wcur + nt * 2304 + boff);

        if (c + 1 < NCHUNK) copyW(c + 1, nxt);

        #pragma unroll
        for (int ks = 0; ks < 4; ks++) {
            const int cb = ks & 1, nb = cb ^ 1;
            if (ks < 3) {   // prefetch next slice while this slice's MMAs run
                #pragma unroll
                for (int mt = 0; mt < 2; mt++)
                    ldsm4(aF[nb][mt], ycur + mt * 2304 + (ks + 1) * 32 + aoff);
                #pragma unroll
                for (int nt = 0; nt < 4; nt++)
                    ldsm4(bF[nb][nt], wcur + nt * 2304 + (ks + 1) * 32 + boff);
            }
            #pragma unroll
            for (int mt = 0; mt < 2; mt++)
                #pragma unroll
                for (int j = 0; j < 8; j++)
                    mma16816(acc[mt][j], aF[cb][mt], bF[cb][j >> 1][(j & 1) * 2],
                             bF[cb][j >> 1][(j & 1) * 2 + 1]);
        }

        if (c + 1 < NCHUNK) buildY(c + 1, nxt);

        asm volatile("cp.async.wait_group 0;" ::: "memory");
        __syncthreads();
    }

    // ---- epilogue: transpose via smem, coalesced stores, undo 64*64 scale ----
    const float inv = 1.0f / 4096.0f;
    float* buf = (float*)smem;                       // [64][136] fp32
    float* ob  = out + ((size_t)b * OUT_CH) * HW + hw0;
    #pragma unroll 1
    for (int slab = 0; slab < 4; slab++) {
        __syncthreads();
        if (wn == slab) {
            #pragma unroll
            for (int mt = 0; mt < 2; mt++)
                #pragma unroll
                for (int j = 0; j < 8; j++) {
                    int px = wm * 32 + mt * 16 + (lane >> 2);
                    int ch = j * 8 + (lane & 3) * 2;
                    buf[ch * 136 + px]           = acc[mt][j][0] * inv;
                    buf[(ch + 1) * 136 + px]     = acc[mt][j][1] * inv;
                    buf[ch * 136 + px + 8]       = acc[mt][j][2] * inv;
                    buf[(ch + 1) * 136 + px + 8] = acc[mt][j][3] * inv;
                }
        }
        __syncthreads();
        #pragma unroll
        for (int t = 0; t < 4; t++) {
            int e   = tid + t * NTH;                 // 0..2047
            int chl = e >> 5;
            int po  = (e & 31) << 2;
            float4 v = *(float4*)(buf + chl * 136 + po);
            *(float4*)(ob + (size_t)(slab * 64 + chl) * HW + po) = v;
        }
    }
}

// ---------------- launch ----------------
extern "C" void kernel_launch(void* const* d_in, const int* in_sizes, int n_in,
                              void* d_out, int out_size) {
    const float* x = (const float*)d_in[0];    // [B, 64, 64, 64] fp32
    const float* w = (const float*)d_in[1];    // [256, 2144] fp32
    float* out = (float*)d_out;                // [B, 256, 64, 64] fp32

    int pixels = in_sizes[0] / C_CH;           // B * 4096

    cudaFuncSetAttribute(quad_hmma_kernel,
                         cudaFuncAttributeMaxDynamicSharedMemorySize, SM_TOT);

    w_prep_kernel<<<NCHUNK, 256>>>(w);
    quad_hmma_kernel<<<pixels / PX_CTA, NTH, SM_TOT>>>(x, out);
}

// round 7
// speedup vs baseline: 9.5809x; 1.0841x over previous
#include <cuda_runtime.h>
#include <cuda_fp16.h>
#include <cstdint>

#define C_CH     64
#define NIN      2144
#define NINP     2176        // padded to 34*64
#define OUT_CH   256
#define HW       4096
#define KC       64
#define NCHUNK   34
#define PX_CTA   128
#define NTH      512

// ---------------- prep storage (device globals) ----------------
// W per chunk: [chunk][n=256][128B row], SW128 pre-swizzled fp16, zero-padded.
#define WCHUNK_BYTES 32768
__device__ __align__(16) unsigned char g_w[NCHUNK * WCHUNK_BYTES];
__device__ __align__(16) uchar2 g_pairs[NINP];   // {i, j}; j==64 => constant-1 channel

// ---------------- smem layout (dynamic) ----------------
// XS : x tile [65 ch][128 px] fp32 (row 64 = 1.0f)  = 33280 B
// Y  : 2 stages x [128 px][128 B] fp16 SW128        = 2 x 16384 B
// W  : 2 stages x [256 n ][128 B] fp16 SW128        = 2 x 32768 B
// PS : pair table 2176 uchar2                       =  4352 B
// Epilogue reuses [0, 34816) as fp32 [64][136] buffer.
#define SM_XS    0
#define SM_Y     33280
#define Y_STAGE  16384
#define SM_W     66048
#define W_STAGE  32768
#define SM_PS    131584
#define SM_TOT   135936

// ---------------- asm helpers ----------------
__device__ __forceinline__ void ldsm4(uint32_t (&r)[4], uint32_t addr) {
    asm volatile("ldmatrix.sync.aligned.m8n8.x4.shared.b16 {%0,%1,%2,%3}, [%4];"
                 : "=r"(r[0]), "=r"(r[1]), "=r"(r[2]), "=r"(r[3]) : "r"(addr));
}
__device__ __forceinline__ void mma16816(float (&c)[4], const uint32_t (&a)[4],
                                         uint32_t b0, uint32_t b1) {
    asm volatile(
        "mma.sync.aligned.m16n8k16.row.col.f32.f16.f16.f32 "
        "{%0,%1,%2,%3}, {%4,%5,%6,%7}, {%8,%9}, {%0,%1,%2,%3};"
        : "+f"(c[0]), "+f"(c[1]), "+f"(c[2]), "+f"(c[3])
        : "r"(a[0]), "r"(a[1]), "r"(a[2]), "r"(a[3]), "r"(b0), "r"(b1));
}
__device__ __forceinline__ void cp_async16(uint32_t saddr, const void* gptr) {
    asm volatile("cp.async.cg.shared.global [%0], [%1], 16;"
                 :: "r"(saddr), "l"(gptr) : "memory");
}

// ---------------- prep kernel (pairs + W convert+swizzle, one launch) ----------------
__global__ void w_prep_kernel(const float* __restrict__ w) {
    int c = blockIdx.x;              // chunk 0..33
    int n = threadIdx.x;             // output row 0..255

    if (c == 0 && n < C_CH) {        // pair table; linear channels pair with ones-row 64
        int i = n;
        g_pairs[i] = make_uchar2((unsigned char)i, 64);
        int base = C_CH + C_CH * i - (i * (i - 1)) / 2;
        for (int j = i; j < C_CH; j++)
            g_pairs[base + (j - i)] = make_uchar2((unsigned char)i, (unsigned char)j);
    }
    if (c == 0 && n >= 64 && n < 96)             // padding pairs (W is zero there)
        g_pairs[NIN + (n - 64)] = make_uchar2(0, 64);

    const float* wr = w + (size_t)n * NIN;
    unsigned char* wb = g_w + (size_t)c * WCHUNK_BYTES + n * 128;
    #pragma unroll
    for (int kp = 0; kp < 32; kp++) {
        int k  = c * KC + 2 * kp;
        float f0 = (k     < NIN) ? wr[k]     : 0.0f;
        float f1 = (k + 1 < NIN) ? wr[k + 1] : 0.0f;
        __half2 h2 = __float22half2_rn(make_float2(f0, f1));
        int kl = 2 * kp;
        int phys = (((kl >> 3) ^ (n & 7)) << 4) + (kl & 7) * 2;   // SW128
        *(uint32_t*)(wb + phys) = *(uint32_t*)&h2;
    }
}

// ---------------- main kernel ----------------
__global__ __launch_bounds__(NTH, 1)
void quad_hmma_kernel(const float* __restrict__ x, float* __restrict__ out) {
    extern __shared__ __align__(1024) unsigned char smem[];
    const int tid  = threadIdx.x;
    const int wid  = tid >> 5;
    const int lane = tid & 31;
    const int wm   = wid >> 2;          // warp row (M): 0..3, 32 px each
    const int wn   = wid & 3;           // warp col (N): 0..3, 64 ch each
    const uint32_t sb = (uint32_t)__cvta_generic_to_shared(smem);

    float*  xs = (float*)(smem + SM_XS);
    uchar2* ps = (uchar2*)(smem + SM_PS);

    // ---- global pixel tile ----
    const int p0  = blockIdx.x * PX_CTA;
    const int b   = p0 >> 12;
    const int hw0 = p0 & 4095;
    const float* xb = x + (((size_t)b * C_CH) << 12) + hw0;

    // ---- load x tile: 64 ch x 128 px (2048 float4, 4/thread) + ones row ----
    #pragma unroll
    for (int t = 0; t < 4; t++) {
        int e  = tid + t * NTH;
        int ch = e >> 5;
        int po = (e & 31) << 2;
        *(float4*)(xs + ch * 128 + po) = *(const float4*)(xb + ((size_t)ch << 12) + po);
    }
    if (tid < 32) *(float4*)(xs + 64 * 128 + tid * 4) = make_float4(1.f, 1.f, 1.f, 1.f);
    if (tid < NINP / 8) ((uint4*)ps)[tid] = ((const uint4*)g_pairs)[tid];
    __syncthreads();

    // ---- per-lane swizzled ldmatrix row bases ----
    const uint32_t l7    = lane & 7;
    const uint32_t aRow  = (uint32_t)(wm * 32 + (lane & 15)) * 128;
    const uint32_t aHalf = (uint32_t)(lane >> 4);
    const uint32_t bRow  = (uint32_t)(wn * 64 + ((lane >> 4) << 3) + (lane & 7)) * 128;
    const uint32_t bHalf = (uint32_t)((lane >> 3) & 1);

    float acc[2][8][4];
    #pragma unroll
    for (int mt = 0; mt < 2; mt++)
        #pragma unroll
        for (int j = 0; j < 8; j++)
            #pragma unroll
            for (int q = 0; q < 4; q++) acc[mt][j][q] = 0.0f;

    const int pY  = tid & 127;          // pixel this thread builds
    const int q16 = tid >> 7;           // which 16-k group (0..3)
    const float* xcol = xs + pY;

    // ---- copy W chunk (linear; g_w pre-swizzled) ----
    auto copyW = [&](int cc, int stage) {
        const unsigned char* src = g_w + (size_t)cc * WCHUNK_BYTES;
        uint32_t dst = sb + SM_W + stage * W_STAGE;
        #pragma unroll
        for (int t = 0; t < 4; t++) {
            uint32_t off = (uint32_t)(tid + t * NTH) * 16;
            cp_async16(dst + off, src + off);
        }
        asm volatile("cp.async.commit_group;" ::: "memory");
    };

    // ---- build Y: load phase (pairs + x -> 8 packed half2) ----
    auto buildLoad = [&](int cc, uint32_t* yv) {
        const uint4* pp = (const uint4*)((const unsigned char*)ps + cc * 128 + q16 * 32);
        uint4 P0 = pp[0], P1 = pp[1];
        uint32_t wsrc[8] = {P0.x, P0.y, P0.z, P0.w, P1.x, P1.y, P1.z, P1.w};
        #pragma unroll
        for (int q = 0; q < 8; q++) {
            uint32_t w_ = wsrc[q];
            float a0 = xcol[(w_ & 255u) << 7];
            float b0 = xcol[((w_ >> 8) & 255u) << 7];
            float a1 = xcol[((w_ >> 16) & 255u) << 7];
            float b1 = xcol[(w_ >> 24) << 7];
            __half2 h = __float22half2_rn(make_float2(a0 * b0, a1 * b1));
            yv[q] = *(uint32_t*)&h;
        }
    };
    // ---- build Y: store phase (2 x STS.128, SW128) ----
    auto buildStore = [&](int stage, const uint32_t* yv) {
        unsigned char* yb = smem + SM_Y + stage * Y_STAGE + pY * 128;
        uint32_t s0 = (uint32_t)(((q16 * 2)     ^ (pY & 7)) << 4);
        uint32_t s1 = (uint32_t)(((q16 * 2 + 1) ^ (pY & 7)) << 4);
        *(uint4*)(yb + s0) = make_uint4(yv[0], yv[1], yv[2], yv[3]);
        *(uint4*)(yb + s1) = make_uint4(yv[4], yv[5], yv[6], yv[7]);
    };

    // ---- prologue: stage 0 ----
    copyW(0, 0);
    {
        uint32_t yv0[8];
        buildLoad(0, yv0);
        buildStore(0, yv0);
    }
    asm volatile("cp.async.wait_group 0;" ::: "memory");
    __syncthreads();

    uint32_t aF[2][4], bF[4][4], yv[8];

#define LDA(ks) { _Pragma("unroll") for (int mt = 0; mt < 2; mt++) \
    ldsm4(aF[mt], ycur + aRow + mt * 2048 + (((((ks) * 2) + aHalf) ^ l7) << 4)); }
#define LDB(ks) { _Pragma("unroll") for (int nt = 0; nt < 4; nt++) \
    ldsm4(bF[nt], wcur + bRow + nt * 2048 + (((((ks) * 2) + bHalf) ^ l7) << 4)); }
#define DOMMA() { _Pragma("unroll") for (int mt = 0; mt < 2; mt++) \
    _Pragma("unroll") for (int j = 0; j < 8; j++) \
        mma16816(acc[mt][j], aF[mt], bF[j >> 1][(j & 1) * 2], bF[j >> 1][(j & 1) * 2 + 1]); }

    for (int c = 0; c < NCHUNK; c++) {
        const int cur = c & 1;
        const int nxt = cur ^ 1;
        const uint32_t ycur = sb + SM_Y + cur * Y_STAGE;
        const uint32_t wcur = sb + SM_W + cur * W_STAGE;
        const bool more = (c + 1 < NCHUNK);

        LDA(0); LDB(0);
        if (more) copyW(c + 1, nxt);
        DOMMA();
        LDA(1); LDB(1);
        if (more) buildLoad(c + 1, yv);      // latency hides under slices 1-3
        DOMMA();
        LDA(2); LDB(2);
        DOMMA();
        LDA(3); LDB(3);
        DOMMA();
        if (more) buildStore(nxt, yv);

        asm volatile("cp.async.wait_group 0;" ::: "memory");
        __syncthreads();
    }
#undef LDA
#undef LDB
#undef DOMMA

    // ---- epilogue: transpose via smem, coalesced stores ----
    float* buf = (float*)smem;                       // [64][136] fp32
    float* ob  = out + ((size_t)b * OUT_CH) * HW + hw0;
    #pragma unroll 1
    for (int slab = 0; slab < 4; slab++) {
        __syncthreads();
        if (wn == slab) {
            #pragma unroll
            for (int mt = 0; mt < 2; mt++)
                #pragma unroll
                for (int j = 0; j < 8; j++) {
                    int px = wm * 32 + mt * 16 + (lane >> 2);
                    int ch = j * 8 + (lane & 3) * 2;
                    buf[ch * 136 + px]           = acc[mt][j][0];
                    buf[(ch + 1) * 136 + px]     = acc[mt][j][1];
                    buf[ch * 136 + px + 8]       = acc[mt][j][2];
                    buf[(ch + 1) * 136 + px + 8] = acc[mt][j][3];
                }
        }
        __syncthreads();
        #pragma unroll
        for (int t = 0; t < 4; t++) {
            int e   = tid + t * NTH;                 // 0..2047
            int chl = e >> 5;
            int po  = (e & 31) << 2;
            float4 v = *(float4*)(buf + chl * 136 + po);
            *(float4*)(ob + (size_t)(slab * 64 + chl) * HW + po) = v;
        }
    }
}

// ---------------- launch ----------------
extern "C" void kernel_launch(void* const* d_in, const int* in_sizes, int n_in,
                              void* d_out, int out_size) {
    const float* x = (const float*)d_in[0];    // [B, 64, 64, 64] fp32
    const float* w = (const float*)d_in[1];    // [256, 2144] fp32
    float* out = (float*)d_out;                // [B, 256, 64, 64] fp32

    int pixels = in_sizes[0] / C_CH;           // B * 4096

    cudaFuncSetAttribute(quad_hmma_kernel,
                         cudaFuncAttributeMaxDynamicSharedMemorySize, SM_TOT);

    w_prep_kernel<<<NCHUNK, 256>>>(w);
    quad_hmma_kernel<<<pixels / PX_CTA, NTH, SM_TOT>>>(x, out);
}